// round 9
// baseline (speedup 1.0000x reference)
#include <cuda_runtime.h>
#include <cstdint>

// Problem constants (from reference)
#define E_NUM 128
#define R_NUM 65536
#define S_NUM 100000
#define ER (E_NUM * R_NUM)          // 8,388,608 floats per table

// Interleaved scratch accumulator: scratch[2*(e*R+r)+0] = delta-a,
//                                  scratch[2*(e*R+r)+1] = delta-b
// 2*ER floats = 64 MiB, static device global (no allocation).
__device__ float g_scratch[2u * ER];

// ---------------------------------------------------------------------------
// Scatter for estimator quarter Q (e in [32Q, 32Q+32)).
// One thread per 4 (sample, estimator) pairs: int4 sr load covers e0..e0+3 of
// one sample (8 threads = 128B contiguous chunk per sample); da/db broadcast.
// 4x red.global.add.v2.f32 per thread. 3.2M RED ops per quarter ->
// ~15.5us at the 1.29 cyc/op spread-REDG floor.
// ---------------------------------------------------------------------------
template <int Q>
__global__ void __launch_bounds__(256) scatter_q_kernel(
        const int4* __restrict__ sr4,
        const float* __restrict__ da,
        const float* __restrict__ db) {
    int t = blockIdx.x * blockDim.x + threadIdx.x;   // [0, S*8) exact grid
    int s = t >> 3;                                  // sample
    int j = t & 7;                                   // int4 slot within quarter
    int4 r = __ldg(sr4 + s * 32 + Q * 8 + j);        // coalesced 128B chunks
    float va = __ldg(da + s);                        // broadcast (4 samples/warp)
    float vb = __ldg(db + s);
    int e0 = 32 * Q + 4 * j;                         // first estimator of the 4

    float* base = g_scratch + 2u * (size_t)e0 * R_NUM;
    float* p0 = base + 2u * (size_t)r.x;
    float* p1 = base + 2u * ((size_t)R_NUM + (size_t)r.y);
    float* p2 = base + 2u * (2u * (size_t)R_NUM + (size_t)r.z);
    float* p3 = base + 2u * (3u * (size_t)R_NUM + (size_t)r.w);
    asm volatile("red.global.add.v2.f32 [%0], {%1, %2};" :: "l"(p0), "f"(va), "f"(vb) : "memory");
    asm volatile("red.global.add.v2.f32 [%0], {%1, %2};" :: "l"(p1), "f"(va), "f"(vb) : "memory");
    asm volatile("red.global.add.v2.f32 [%0], {%1, %2};" :: "l"(p2), "f"(va), "f"(vb) : "memory");
    asm volatile("red.global.add.v2.f32 [%0], {%1, %2};" :: "l"(p3), "f"(va), "f"(vb) : "memory");
}

// ---------------------------------------------------------------------------
// Merge (full width, unchanged from champion): out[0] = a + scratch.a,
// out[1] = b + scratch.b (deinterleave). ~7.6 TB/s — at roofline.
// ---------------------------------------------------------------------------
__global__ void __launch_bounds__(256) merge_kernel(
        const float4* __restrict__ a,
        const float4* __restrict__ b,
        float4* __restrict__ out) {
    int i = blockIdx.x * blockDim.x + threadIdx.x;   // [0, ER/4) exact grid
    const float4* s4 = reinterpret_cast<const float4*>(g_scratch);
    float4 p0 = s4[2 * i + 0];   // {a0,b0,a1,b1}
    float4 p1 = s4[2 * i + 1];   // {a2,b2,a3,b3}
    float4 va = __ldcs(a + i);
    float4 vb = __ldcs(b + i);
    __stcs(out + i,
           make_float4(va.x + p0.x, va.y + p0.z, va.z + p1.x, va.w + p1.z));
    __stcs(out + ER / 4 + i,
           make_float4(vb.x + p0.y, vb.y + p0.w, vb.z + p1.y, vb.w + p1.w));
}

extern "C" void kernel_launch(void* const* d_in, const int* in_sizes, int n_in,
                              void* d_out, int out_size) {
    const float* a  = (const float*)d_in[0];          // [E, R]
    const float* b  = (const float*)d_in[1];          // [E, R]
    const int*   sr = (const int*)d_in[2];            // [S, E]
    const float* da = (const float*)d_in[3];          // [S]
    const float* db = (const float*)d_in[4];          // [S]
    float* out = (float*)d_out;                       // [2, E, R]
    const int4* sr4 = (const int4*)sr;

    // One-time host-side resources (no device memory allocated).
    static char* sp = [] {
        void* p = nullptr;
        cudaGetSymbolAddress(&p, g_scratch);
        return (char*)p;
    }();
    static cudaStream_t s2 = [] {
        cudaStream_t s; cudaStreamCreateWithFlags(&s, cudaStreamNonBlocking);
        return s;
    }();
    static cudaEvent_t ev_root = [] {
        cudaEvent_t e; cudaEventCreateWithFlags(&e, cudaEventDisableTiming);
        return e;
    }();
    static cudaEvent_t m1 = [] {
        cudaEvent_t e; cudaEventCreateWithFlags(&e, cudaEventDisableTiming);
        return e;
    }();
    static cudaEvent_t m2 = [] {
        cudaEvent_t e; cudaEventCreateWithFlags(&e, cudaEventDisableTiming);
        return e;
    }();
    static cudaEvent_t m3 = [] {
        cudaEvent_t e; cudaEventCreateWithFlags(&e, cudaEventDisableTiming);
        return e;
    }();

    const size_t QBYTES = sizeof(float) * 2u * ER / 4;   // 16 MiB per e-quarter
    const int SC_BLOCKS = S_NUM * 8 / 256;               // 3125 exact
    const int MG_BLOCKS = ER / 4 / 256;                  // 8192 exact

    // LEGAL FORK: s2's first captured op is a wait on an event recorded in
    // the capture stream. Then the three side-memsets run concurrently with
    // scatter q0/q1 (LSU-bound, DRAM mostly idle).
    cudaEventRecord(ev_root, 0);
    cudaStreamWaitEvent(s2, ev_root, 0);
    cudaMemsetAsync(sp + 1 * QBYTES, 0, QBYTES, s2);
    cudaEventRecord(m1, s2);
    cudaMemsetAsync(sp + 2 * QBYTES, 0, QBYTES, s2);
    cudaEventRecord(m2, s2);
    cudaMemsetAsync(sp + 3 * QBYTES, 0, QBYTES, s2);
    cudaEventRecord(m3, s2);

    // Main stream: only quarter 0's memset (16 MiB, ~3us) on critical path.
    cudaMemsetAsync(sp, 0, QBYTES, 0);
    scatter_q_kernel<0><<<SC_BLOCKS, 256>>>(sr4, da, db);
    cudaStreamWaitEvent(0, m1, 0);
    scatter_q_kernel<1><<<SC_BLOCKS, 256>>>(sr4, da, db);
    cudaStreamWaitEvent(0, m2, 0);
    scatter_q_kernel<2><<<SC_BLOCKS, 256>>>(sr4, da, db);
    cudaStreamWaitEvent(0, m3, 0);
    scatter_q_kernel<3><<<SC_BLOCKS, 256>>>(sr4, da, db);

    // Merge full-width (all scatter quarters complete on this stream).
    merge_kernel<<<MG_BLOCKS, 256>>>((const float4*)a, (const float4*)b,
                                     (float4*)out);
}

// round 10
// speedup vs baseline: 1.1276x; 1.1276x over previous
#include <cuda_runtime.h>
#include <cstdint>

// Problem constants (from reference)
#define E_NUM 128
#define R_NUM 65536
#define S_NUM 100000
#define ER (E_NUM * R_NUM)          // 8,388,608 floats per table

// Interleaved scratch accumulator: scratch[2*(e*R+r)+0] = delta-a,
//                                  scratch[2*(e*R+r)+1] = delta-b
// 2*ER floats = 64 MiB, static device global (no allocation).
__device__ float g_scratch[2u * ER];

// ---------------------------------------------------------------------------
// Kernel 1: scatter-add (MONOLITHIC — splitting pays ~4-5us RED-drain per
// piece, measured R6/R9). One thread per 4 (sample, estimator) pairs; int4 sr
// load covers e..e+3 of one sample; da/db broadcast. 4x red.global.add.v2.f32.
// 12.8M RED lanes at the 1.29 cyc/lane SM-LSU spread-REDG floor: 62us.
// ---------------------------------------------------------------------------
__global__ void __launch_bounds__(256) scatter_v2x4_kernel(
        const int4* __restrict__ sr4,
        const float* __restrict__ da,
        const float* __restrict__ db) {
    int t = blockIdx.x * blockDim.x + threadIdx.x;   // [0, S*E/4) exact grid
    int e0 = (t & 31) << 2;                          // e = e0..e0+3
    int s  = t >> 5;                                 // warp-uniform
    int4 r = __ldg(sr4 + t);                         // coalesced 16B
    float va = __ldg(da + s);                        // broadcast
    float vb = __ldg(db + s);

    float* base = g_scratch + 2u * (size_t)e0 * R_NUM;
    float* p0 = base + 2u * (size_t)r.x;
    float* p1 = base + 2u * ((size_t)R_NUM + (size_t)r.y);
    float* p2 = base + 2u * (2u * (size_t)R_NUM + (size_t)r.z);
    float* p3 = base + 2u * (3u * (size_t)R_NUM + (size_t)r.w);
    asm volatile("red.global.add.v2.f32 [%0], {%1, %2};" :: "l"(p0), "f"(va), "f"(vb) : "memory");
    asm volatile("red.global.add.v2.f32 [%0], {%1, %2};" :: "l"(p1), "f"(va), "f"(vb) : "memory");
    asm volatile("red.global.add.v2.f32 [%0], {%1, %2};" :: "l"(p2), "f"(va), "f"(vb) : "memory");
    asm volatile("red.global.add.v2.f32 [%0], {%1, %2};" :: "l"(p3), "f"(va), "f"(vb) : "memory");
}

// ---------------------------------------------------------------------------
// Kernel 2: merge: out[0] = a + scratch.a (deinterleave), out[1] = b +
// scratch.b. scratch reads L2-warm; a/b cold -> __ldcs; out -> __stcs.
// 192 MiB DRAM-minimum at ~7.7 TB/s — at roofline.
// ---------------------------------------------------------------------------
__global__ void __launch_bounds__(256) merge_kernel(
        const float4* __restrict__ a,
        const float4* __restrict__ b,
        float4* __restrict__ out) {
    int i = blockIdx.x * blockDim.x + threadIdx.x;   // [0, ER/4) exact grid
    const float4* s4 = reinterpret_cast<const float4*>(g_scratch);
    float4 p0 = s4[2 * i + 0];   // {a0,b0,a1,b1}
    float4 p1 = s4[2 * i + 1];   // {a2,b2,a3,b3}
    float4 va = __ldcs(a + i);
    float4 vb = __ldcs(b + i);
    __stcs(out + i,
           make_float4(va.x + p0.x, va.y + p0.z, va.z + p1.x, va.w + p1.z));
    __stcs(out + ER / 4 + i,
           make_float4(vb.x + p0.y, vb.y + p0.w, vb.z + p1.y, vb.w + p1.w));
}

extern "C" void kernel_launch(void* const* d_in, const int* in_sizes, int n_in,
                              void* d_out, int out_size) {
    const float* a  = (const float*)d_in[0];          // [E, R]
    const float* b  = (const float*)d_in[1];          // [E, R]
    const int*   sr = (const int*)d_in[2];            // [S, E]
    const float* da = (const float*)d_in[3];          // [S]
    const float* db = (const float*)d_in[4];          // [S]
    float* out = (float*)d_out;                       // [2, E, R]

    // One-time host-side resources (no device memory allocated).
    static char* sp = [] {
        void* p = nullptr;
        cudaGetSymbolAddress(&p, g_scratch);
        return (char*)p;
    }();
    static cudaStream_t s2 = [] {
        cudaStream_t s; cudaStreamCreateWithFlags(&s, cudaStreamNonBlocking);
        return s;
    }();
    static cudaEvent_t ev_root = [] {
        cudaEvent_t e; cudaEventCreateWithFlags(&e, cudaEventDisableTiming);
        return e;
    }();
    static cudaEvent_t ev_ms = [] {
        cudaEvent_t e; cudaEventCreateWithFlags(&e, cudaEventDisableTiming);
        return e;
    }();

    const size_t HBYTES = sizeof(float) * ER;         // 32 MiB (half of scratch)

    // Fill test: two CONCURRENT 32 MiB memsets on forked streams.
    // Legal fork: s2's first captured op waits on ev_root recorded in-capture.
    cudaEventRecord(ev_root, 0);
    cudaStreamWaitEvent(s2, ev_root, 0);
    cudaMemsetAsync(sp + HBYTES, 0, HBYTES, s2);      // half 1 on side stream
    cudaEventRecord(ev_ms, s2);
    cudaMemsetAsync(sp, 0, HBYTES, 0);                // half 0 on main stream
    cudaStreamWaitEvent(0, ev_ms, 0);                 // join before scatter

    // Phase 2: monolithic scatter (12500 blocks exact).
    scatter_v2x4_kernel<<<S_NUM * E_NUM / 4 / 256, 256>>>((const int4*)sr, da, db);

    // Phase 3: merge + deinterleave into output (8192 blocks exact).
    merge_kernel<<<ER / 4 / 256, 256>>>((const float4*)a, (const float4*)b,
                                        (float4*)out);
}